// round 1
// baseline (speedup 1.0000x reference)
#include <cuda_runtime.h>
#include <cuda_bf16.h>
#include <math.h>

#define NB 4
#define NV 16384
#define NK 16
#define NE 32
#define NF 2
#define ND 64
#define NH 4
#define NL 2
#define NITERS 10
#define NEGV (-1e9f)
#define NODES (NB * NV)

// ---------------- scratch (device globals; no allocation allowed) ----------------
__device__ float g_h[NODES * ND];          // node hidden state
__device__ float g_t[(size_t)NODES * NH * ND]; // per-head transformed features
__device__ float g_ssrc[NODES * NH];
__device__ float g_sdst[NODES * NH];
__device__ float g_m[NODES * ND];
__device__ float g_z[NODES * ND];
__device__ float g_rh[NODES * ND];
__device__ float g_nodew[NODES];
__device__ float g_inflow[NODES];

__device__ __forceinline__ float sigmoidf_(float x) { return 1.0f / (1.0f + expf(-x)); }

// acc[0..63] += xk * W_row[0..63], W row read uniformly (broadcast via L1)
__device__ __forceinline__ void mv_acc(const float* __restrict__ Wrow, float xk, float acc[ND]) {
    const float4* w4 = reinterpret_cast<const float4*>(Wrow);
#pragma unroll
    for (int j = 0; j < ND / 4; j++) {
        float4 w = __ldg(w4 + j);
        acc[4 * j + 0] += xk * w.x;
        acc[4 * j + 1] += xk * w.y;
        acc[4 * j + 2] += xk * w.z;
        acc[4 * j + 3] += xk * w.w;
    }
}

// ---------------- encoder: h = tanh(tanh(x@W1+b1)@W2+b2) ----------------
__global__ void k_encoder(const float* __restrict__ emb, const float* __restrict__ feat,
                          const float* __restrict__ W1, const float* __restrict__ b1,
                          const float* __restrict__ W2, const float* __restrict__ b2) {
    int n = blockIdx.x * blockDim.x + threadIdx.x;
    if (n >= NODES) return;
    float acc[ND];
#pragma unroll
    for (int j = 0; j < ND; j++) acc[j] = __ldg(&b1[j]);
    const float* x = emb + (size_t)n * NE;
#pragma unroll 4
    for (int k = 0; k < NE; k++) mv_acc(W1 + k * ND, __ldg(&x[k]), acc);
    const float* f = feat + (size_t)n * NF;
#pragma unroll
    for (int k = 0; k < NF; k++) mv_acc(W1 + (NE + k) * ND, __ldg(&f[k]), acc);
    float xl[ND];  // local-mem (lane-interleaved, coalesced LDL)
#pragma unroll
    for (int j = 0; j < ND; j++) { xl[j] = tanhf(acc[j]); acc[j] = __ldg(&b2[j]); }
#pragma unroll 4
    for (int k = 0; k < ND; k++) mv_acc(W2 + k * ND, xl[k], acc);
    float* out = g_h + (size_t)n * ND;
#pragma unroll
    for (int j = 0; j < ND; j++) out[j] = tanhf(acc[j]);
}

// ---------------- GAT: t = h @ W_gat[hd]; s_src/s_dst dot products ----------------
__global__ void k_gat_t(const float* __restrict__ Wgat, const float* __restrict__ asrc,
                        const float* __restrict__ adst) {
    int n = blockIdx.x * blockDim.x + threadIdx.x;
    if (n >= NODES) return;
    float xl[ND];
    const float4* hrow = reinterpret_cast<const float4*>(g_h + (size_t)n * ND);
#pragma unroll
    for (int j = 0; j < ND / 4; j++) {
        float4 v = hrow[j];
        xl[4 * j] = v.x; xl[4 * j + 1] = v.y; xl[4 * j + 2] = v.z; xl[4 * j + 3] = v.w;
    }
    for (int hd = 0; hd < NH; hd++) {
        float acc[ND];
#pragma unroll
        for (int j = 0; j < ND; j++) acc[j] = 0.0f;
        const float* W = Wgat + (size_t)hd * ND * ND;
#pragma unroll 4
        for (int k = 0; k < ND; k++) mv_acc(W + k * ND, xl[k], acc);
        float ss = 0.0f, sd = 0.0f;
        float* trow = g_t + ((size_t)n * NH + hd) * ND;
#pragma unroll
        for (int j = 0; j < ND; j++) {
            ss += acc[j] * __ldg(&asrc[hd * ND + j]);
            sd += acc[j] * __ldg(&adst[hd * ND + j]);
            trow[j] = acc[j];
        }
        g_ssrc[n * NH + hd] = ss;
        g_sdst[n * NH + hd] = sd;
    }
}

// ---------------- GAT attention + aggregation: one CTA per node, one warp per head ----------------
__global__ void k_gat_attn(const int* __restrict__ adj) {
    int n = blockIdx.x;
    int b = n / NV;
    int hd = threadIdx.x >> 5;
    int lane = threadIdx.x & 31;
    __shared__ float s_agg[NH][ND];

    float score = NEGV;
    int idx = NV;
    if (lane < NK) {
        idx = __ldg(&adj[(size_t)n * NK + lane]);
        if (idx < NV)
            score = __ldg(&g_ssrc[n * NH + hd]) + __ldg(&g_sdst[((size_t)b * NV + idx) * NH + hd]);
    }
    float mx = score;
#pragma unroll
    for (int o = 16; o > 0; o >>= 1) mx = fmaxf(mx, __shfl_xor_sync(0xffffffffu, mx, o));
    float e = (lane < NK) ? expf(score - mx) : 0.0f;
    float s = e;
#pragma unroll
    for (int o = 16; o > 0; o >>= 1) s += __shfl_xor_sync(0xffffffffu, s, o);
    float attn = e / s;

    float ax = 0.0f, ay = 0.0f;
#pragma unroll
    for (int k = 0; k < NK; k++) {
        int j = __shfl_sync(0xffffffffu, idx, k);
        float a = __shfl_sync(0xffffffffu, attn, k);
        if (j < NV) {
            const float2* tp =
                reinterpret_cast<const float2*>(g_t + (((size_t)b * NV + j) * NH + hd) * ND);
            float2 tv = __ldg(tp + lane);
            ax += a * tv.x; ay += a * tv.y;
        }
    }
    s_agg[hd][2 * lane] = ax;
    s_agg[hd][2 * lane + 1] = ay;
    __syncthreads();
    if (threadIdx.x < ND) {
        float t = s_agg[0][threadIdx.x] + s_agg[1][threadIdx.x] +
                  s_agg[2][threadIdx.x] + s_agg[3][threadIdx.x];
        g_m[(size_t)n * ND + threadIdx.x] = tanhf(t * (1.0f / NH));
    }
}

// ---------------- GRU part A: z, r*h ----------------
__global__ void k_gru_zr(const float* __restrict__ Wz, const float* __restrict__ Uz,
                         const float* __restrict__ bz, const float* __restrict__ Wr,
                         const float* __restrict__ Ur, const float* __restrict__ br) {
    int n = blockIdx.x * blockDim.x + threadIdx.x;
    if (n >= NODES) return;
    float ml[ND], hl[ND];
    {
        const float4* mr = reinterpret_cast<const float4*>(g_m + (size_t)n * ND);
        const float4* hr = reinterpret_cast<const float4*>(g_h + (size_t)n * ND);
#pragma unroll
        for (int j = 0; j < ND / 4; j++) {
            float4 v = mr[j];
            ml[4 * j] = v.x; ml[4 * j + 1] = v.y; ml[4 * j + 2] = v.z; ml[4 * j + 3] = v.w;
            float4 w = hr[j];
            hl[4 * j] = w.x; hl[4 * j + 1] = w.y; hl[4 * j + 2] = w.z; hl[4 * j + 3] = w.w;
        }
    }
    float acc[ND];
    // z
#pragma unroll
    for (int j = 0; j < ND; j++) acc[j] = __ldg(&bz[j]);
#pragma unroll 4
    for (int k = 0; k < ND; k++) mv_acc(Wz + k * ND, ml[k], acc);
#pragma unroll 4
    for (int k = 0; k < ND; k++) mv_acc(Uz + k * ND, hl[k], acc);
    float* zo = g_z + (size_t)n * ND;
#pragma unroll
    for (int j = 0; j < ND; j++) zo[j] = sigmoidf_(acc[j]);
    // r, rh
#pragma unroll
    for (int j = 0; j < ND; j++) acc[j] = __ldg(&br[j]);
#pragma unroll 4
    for (int k = 0; k < ND; k++) mv_acc(Wr + k * ND, ml[k], acc);
#pragma unroll 4
    for (int k = 0; k < ND; k++) mv_acc(Ur + k * ND, hl[k], acc);
    float* ro = g_rh + (size_t)n * ND;
#pragma unroll
    for (int j = 0; j < ND; j++) ro[j] = sigmoidf_(acc[j]) * hl[j];
}

// ---------------- GRU part B: c + state update ----------------
__global__ void k_gru_c(const float* __restrict__ Wc, const float* __restrict__ Uc,
                        const float* __restrict__ bc) {
    int n = blockIdx.x * blockDim.x + threadIdx.x;
    if (n >= NODES) return;
    float xl[ND];
    {
        const float4* mr = reinterpret_cast<const float4*>(g_m + (size_t)n * ND);
#pragma unroll
        for (int j = 0; j < ND / 4; j++) {
            float4 v = mr[j];
            xl[4 * j] = v.x; xl[4 * j + 1] = v.y; xl[4 * j + 2] = v.z; xl[4 * j + 3] = v.w;
        }
    }
    float acc[ND];
#pragma unroll
    for (int j = 0; j < ND; j++) acc[j] = __ldg(&bc[j]);
#pragma unroll 4
    for (int k = 0; k < ND; k++) mv_acc(Wc + k * ND, xl[k], acc);
    {
        const float4* rr = reinterpret_cast<const float4*>(g_rh + (size_t)n * ND);
#pragma unroll
        for (int j = 0; j < ND / 4; j++) {
            float4 v = rr[j];
            xl[4 * j] = v.x; xl[4 * j + 1] = v.y; xl[4 * j + 2] = v.z; xl[4 * j + 3] = v.w;
        }
    }
#pragma unroll 4
    for (int k = 0; k < ND; k++) mv_acc(Uc + k * ND, xl[k], acc);
    float* hrow = g_h + (size_t)n * ND;
    const float* zrow = g_z + (size_t)n * ND;
#pragma unroll
    for (int j = 0; j < ND; j++) {
        float c = tanhf(acc[j]);
        float z = zrow[j];
        float h = hrow[j];
        hrow[j] = (1.0f - z) * h + z * c;
    }
}

// ---------------- decoder -> per-node scalar weight ----------------
__global__ void k_decoder(const float* __restrict__ W1, const float* __restrict__ b1,
                          const float* __restrict__ W2, const float* __restrict__ b2) {
    int n = blockIdx.x * blockDim.x + threadIdx.x;
    if (n >= NODES) return;
    float xl[ND];
    {
        const float4* hr = reinterpret_cast<const float4*>(g_h + (size_t)n * ND);
#pragma unroll
        for (int j = 0; j < ND / 4; j++) {
            float4 v = hr[j];
            xl[4 * j] = v.x; xl[4 * j + 1] = v.y; xl[4 * j + 2] = v.z; xl[4 * j + 3] = v.w;
        }
    }
    float acc[ND];
#pragma unroll
    for (int j = 0; j < ND; j++) acc[j] = __ldg(&b1[j]);
#pragma unroll 4
    for (int k = 0; k < ND; k++) mv_acc(W1 + k * ND, xl[k], acc);
    float w = __ldg(&b2[0]);
#pragma unroll
    for (int j = 0; j < ND; j++) w += tanhf(acc[j]) * __ldg(&W2[j]);
    g_nodew[n] = w;
}

// ---------------- edge softmax + flow0; also zero inflow ----------------
__global__ void k_normw(const int* __restrict__ adj, const float* __restrict__ demands,
                        float* __restrict__ out_normw, float* __restrict__ out_flow0) {
    int n = blockIdx.x * blockDim.x + threadIdx.x;
    if (n >= NODES) return;
    int b = n / NV;
    float sc[NK];
    float mx = NEGV;
#pragma unroll
    for (int k = 0; k < NK; k++) {
        int idx = __ldg(&adj[(size_t)n * NK + k]);
        float s = (idx < NV) ? __ldg(&g_nodew[(size_t)b * NV + idx]) : NEGV;
        sc[k] = s;
        mx = fmaxf(mx, s);
    }
    float sum = 0.0f;
#pragma unroll
    for (int k = 0; k < NK; k++) { sc[k] = expf(sc[k] - mx); sum += sc[k]; }
    float inv = 1.0f / sum;
    float supply = fmaxf(-__ldg(&demands[n]), 0.0f);
#pragma unroll
    for (int k = 0; k < NK; k++) {
        float nw = sc[k] * inv;
        out_normw[(size_t)n * NK + k] = nw;
        out_flow0[(size_t)n * NK + k] = nw * supply;
    }
    g_inflow[n] = 0.0f;
}

// ---------------- flow iteration: scatter-add then update (update re-zeros inflow) ----------------
__global__ void k_scatter(const int* __restrict__ adj, const float* __restrict__ flow) {
    int n = blockIdx.x * blockDim.x + threadIdx.x;
    if (n >= NODES) return;
    int b = n / NV;
#pragma unroll
    for (int k = 0; k < NK; k++) {
        int idx = __ldg(&adj[(size_t)n * NK + k]);
        if (idx < NV) atomicAdd(&g_inflow[(size_t)b * NV + idx], __ldg(&flow[(size_t)n * NK + k]));
    }
}

__global__ void k_update(const float* __restrict__ demands, const float* __restrict__ normw,
                         float* __restrict__ nxt) {
    int n = blockIdx.x * blockDim.x + threadIdx.x;
    if (n >= NODES) return;
    float nf = fmaxf(g_inflow[n] - __ldg(&demands[n]), 0.0f);
    g_inflow[n] = 0.0f;
    const float4* nw4 = reinterpret_cast<const float4*>(normw + (size_t)n * NK);
    float4* o4 = reinterpret_cast<float4*>(nxt + (size_t)n * NK);
#pragma unroll
    for (int k = 0; k < NK / 4; k++) {
        float4 v = __ldg(nw4 + k);
        v.x *= nf; v.y *= nf; v.z *= nf; v.w *= nf;
        o4[k] = v;
    }
}

// ---------------- per-batch quadratic cost reduction ----------------
__global__ void k_cost(const float* __restrict__ flow, float* __restrict__ cost) {
    // 256 blocks total, 64 per batch, each block covers 4096 elems
    int b = blockIdx.x >> 6;
    size_t base = (size_t)blockIdx.x * 4096;
    const float4* f4 = reinterpret_cast<const float4*>(flow + base);
    float s = 0.0f;
    for (int i = threadIdx.x; i < 1024; i += 256) {
        float4 v = __ldg(f4 + i);
        s += v.x * v.x + v.y * v.y + v.z * v.z + v.w * v.w;
    }
#pragma unroll
    for (int o = 16; o > 0; o >>= 1) s += __shfl_xor_sync(0xffffffffu, s, o);
    __shared__ float ws[8];
    if ((threadIdx.x & 31) == 0) ws[threadIdx.x >> 5] = s;
    __syncthreads();
    if (threadIdx.x == 0) {
        float t = 0.0f;
        for (int i = 0; i < 8; i++) t += ws[i];
        atomicAdd(&cost[b], t);
    }
}

// ---------------- launch ----------------
extern "C" void kernel_launch(void* const* d_in, const int* in_sizes, int n_in,
                              void* d_out, int out_size) {
    const float* emb     = (const float*)d_in[0];
    const float* feat    = (const float*)d_in[1];
    const float* demands = (const float*)d_in[2];
    const int*   adj     = (const int*)d_in[3];
    // d_in[4] = flow_indices (unused; reference computes inflow by scatter-add)
    int wb = (in_sizes[5] == 1) ? 6 : 5;  // skip scalar num_nodes if present
    const float* W_enc1 = (const float*)d_in[wb + 0];
    const float* b_enc1 = (const float*)d_in[wb + 1];
    const float* W_enc2 = (const float*)d_in[wb + 2];
    const float* b_enc2 = (const float*)d_in[wb + 3];
    const float* W_gat  = (const float*)d_in[wb + 4];
    const float* a_src  = (const float*)d_in[wb + 5];
    const float* a_dst  = (const float*)d_in[wb + 6];
    const float* W_z    = (const float*)d_in[wb + 7];
    const float* U_z    = (const float*)d_in[wb + 8];
    const float* b_z    = (const float*)d_in[wb + 9];
    const float* W_r    = (const float*)d_in[wb + 10];
    const float* U_r    = (const float*)d_in[wb + 11];
    const float* b_r    = (const float*)d_in[wb + 12];
    const float* W_c    = (const float*)d_in[wb + 13];
    const float* U_c    = (const float*)d_in[wb + 14];
    const float* b_c    = (const float*)d_in[wb + 15];
    const float* W_dec1 = (const float*)d_in[wb + 16];
    const float* b_dec1 = (const float*)d_in[wb + 17];
    const float* W_dec2 = (const float*)d_in[wb + 18];
    const float* b_dec2 = (const float*)d_in[wb + 19];

    float* out = (float*)d_out;
    float* out_flow  = out;                       // [B,V,K]  f10
    float* out_cost  = out + (size_t)NB * NV * NK;  // [B]
    float* out_normw = out_cost + NB;             // [B,V,K]
    float* out_pflow = out_normw + (size_t)NB * NV * NK;  // [B,V,K]  f9

    const int T = 256;
    const int G = NODES / T;  // 256

    k_encoder<<<G, T>>>(emb, feat, W_enc1, b_enc1, W_enc2, b_enc2);
    for (int l = 0; l < NL; l++) {
        k_gat_t<<<G, T>>>(W_gat, a_src, a_dst);
        k_gat_attn<<<NODES, NH * 32>>>(adj);
        k_gru_zr<<<G, T>>>(W_z, U_z, b_z, W_r, U_r, b_r);
        k_gru_c<<<G, T>>>(W_c, U_c, b_c);
    }
    k_decoder<<<G, T>>>(W_dec1, b_dec1, W_dec2, b_dec2);
    k_normw<<<G, T>>>(adj, demands, out_normw, out_flow);

    float* cur = out_flow;
    float* nxt = out_pflow;
    for (int it = 0; it < NITERS; it++) {
        k_scatter<<<G, T>>>(adj, cur);
        k_update<<<G, T>>>(demands, out_normw, nxt);
        float* tmp = cur; cur = nxt; nxt = tmp;
    }
    // after 10 iters: f10 in out_flow, f9 in out_pflow (cur == out_flow)

    cudaMemsetAsync(out_cost, 0, NB * sizeof(float), 0);
    k_cost<<<256, 256>>>(out_flow, out_cost);
}

// round 2
// speedup vs baseline: 2.1191x; 2.1191x over previous
#include <cuda_runtime.h>
#include <cuda_bf16.h>
#include <math.h>

#define NB 4
#define NV 16384
#define NK 16
#define NE 32
#define NF 2
#define NDIN 34
#define ND 64
#define NH 4
#define NL 2
#define NITERS 10
#define NEGV (-1e9f)
#define NODES (NB * NV)
#define XP 65  // padded x-tile row stride (65 mod 32 == 1 -> conflict-free)

typedef unsigned long long ull;

// ---------------- scratch (device globals; no allocation allowed) ----------------
__device__ float g_h[NODES * ND];
__device__ float g_t[(size_t)NODES * NH * ND];
__device__ float g_ssrc[NODES * NH];
__device__ float g_sdst[NODES * NH];
__device__ float g_m[NODES * ND];
__device__ float g_z[NODES * ND];
__device__ float g_rh[NODES * ND];
__device__ float g_nodew[NODES];
__device__ float g_inflow[NODES];

__device__ __forceinline__ float sigmoidf_(float x) { return 1.0f / (1.0f + expf(-x)); }

// ---------------- f32x2 packed-FMA helpers (sm_103a) ----------------
__device__ __forceinline__ ull pack2(float x) {
    ull r; asm("mov.b64 %0, {%1, %1};" : "=l"(r) : "f"(x)); return r;
}
__device__ __forceinline__ void ffma2(ull& d, ull a, ull b) {
    asm("fma.rn.f32x2 %0, %1, %2, %0;" : "+l"(d) : "l"(a), "l"(b));
}
__device__ __forceinline__ float2 unpk(ull v) {
    float2 f; asm("mov.b64 {%0, %1}, %2;" : "=f"(f.x), "=f"(f.y) : "l"(v)); return f;
}
__device__ __forceinline__ void acc_init0(ull acc[8]) {
#pragma unroll
    for (int i = 0; i < 8; i++) acc[i] = 0ull;
}
__device__ __forceinline__ void acc_initb(const float* __restrict__ bias, int cbase, ull acc[8]) {
    const ull* b = reinterpret_cast<const ull*>(bias + cbase);
#pragma unroll
    for (int i = 0; i < 8; i++) acc[i] = __ldg(b + i);
}
__device__ __forceinline__ void acc_unpack(const ull acc[8], float f[16]) {
#pragma unroll
    for (int i = 0; i < 8; i++) { float2 p = unpk(acc[i]); f[2 * i] = p.x; f[2 * i + 1] = p.y; }
}

// out[cbase..cbase+15] += sum_k xrow[k] * Ws[k][cbase+j]   (Ws smem [K][64], xrow smem)
template <int K>
__device__ __forceinline__ void gemv_acc(const float* __restrict__ xrow,
                                         const float* __restrict__ Ws,
                                         int cbase, ull acc[8]) {
#pragma unroll 4
    for (int k = 0; k < K; k++) {
        ull xk = pack2(xrow[k]);
        const ulonglong2* wp = reinterpret_cast<const ulonglong2*>(Ws + k * ND + cbase);
        ulonglong2 w0 = wp[0], w1 = wp[1], w2 = wp[2], w3 = wp[3];
        ffma2(acc[0], xk, w0.x); ffma2(acc[1], xk, w0.y);
        ffma2(acc[2], xk, w1.x); ffma2(acc[3], xk, w1.y);
        ffma2(acc[4], xk, w2.x); ffma2(acc[5], xk, w2.y);
        ffma2(acc[6], xk, w3.x); ffma2(acc[7], xk, w3.y);
    }
}

// coalesced copy of 128 rows x 64 floats into padded smem tile
__device__ __forceinline__ void load_tile64(const float* __restrict__ g, float* xs) {
    const float4* g4 = reinterpret_cast<const float4*>(g);
#pragma unroll 4
    for (int i = threadIdx.x; i < 128 * 16; i += 128) {
        float4 v = g4[i];
        int r = i >> 4, c = (i & 15) << 2;
        float* d = xs + r * XP + c;
        d[0] = v.x; d[1] = v.y; d[2] = v.z; d[3] = v.w;
    }
}
__device__ __forceinline__ void load_w(const float* __restrict__ g, float* ws, int nfloats) {
    const float4* g4 = reinterpret_cast<const float4*>(g);
    float4* s4 = reinterpret_cast<float4*>(ws);
    for (int i = threadIdx.x; i < (nfloats >> 2); i += 128) s4[i] = __ldg(g4 + i);
}

// ---------------- encoder ----------------
__global__ void k_encoder(const float* __restrict__ emb, const float* __restrict__ feat,
                          const float* __restrict__ W1, const float* __restrict__ b1,
                          const float* __restrict__ W2, const float* __restrict__ b2) {
    extern __shared__ float sm[];
    float* xsA = sm;                       // 128*35
    float* xsB = sm + 128 * 35;            // 128*65
    float* W1s = xsB + 128 * XP;           // 34*64
    float* W2s = W1s + NDIN * ND;          // 64*64
    int tid = threadIdx.x;
    load_w(W1, W1s, NDIN * ND);
    load_w(W2, W2s, ND * ND);
    for (int rep = 0; rep < 2; rep++) {
        int nb0 = (blockIdx.x + rep * 256) * 128;
        __syncthreads();
        {
            const float4* g4 = reinterpret_cast<const float4*>(emb + (size_t)nb0 * NE);
#pragma unroll 2
            for (int i = tid; i < 128 * 8; i += 128) {
                float4 v = g4[i];
                int r = i >> 3, c = (i & 7) << 2;
                float* d = xsA + r * 35 + c;
                d[0] = v.x; d[1] = v.y; d[2] = v.z; d[3] = v.w;
            }
            const float2* f2 = reinterpret_cast<const float2*>(feat + (size_t)nb0 * NF);
            {
                float2 v = f2[tid];
                float* d = xsA + tid * 35 + 32;
                d[0] = v.x; d[1] = v.y;
            }
        }
        __syncthreads();
        const float* xrow = xsA + tid * 35;
        float* brow = xsB + tid * XP;
#pragma unroll
        for (int c = 0; c < 4; c++) {
            ull acc[8]; acc_initb(b1, c * 16, acc);
            gemv_acc<NDIN>(xrow, W1s, c * 16, acc);
            float f[16]; acc_unpack(acc, f);
#pragma unroll
            for (int j = 0; j < 16; j++) brow[c * 16 + j] = tanhf(f[j]);
        }
        // each thread reads only its own xsB row -> no sync needed
        float* out = g_h + (size_t)(nb0 + tid) * ND;
#pragma unroll
        for (int c = 0; c < 4; c++) {
            ull acc[8]; acc_initb(b2, c * 16, acc);
            gemv_acc<ND>(brow, W2s, c * 16, acc);
            float f[16]; acc_unpack(acc, f);
            float4* o4 = reinterpret_cast<float4*>(out + c * 16);
            o4[0] = make_float4(tanhf(f[0]), tanhf(f[1]), tanhf(f[2]), tanhf(f[3]));
            o4[1] = make_float4(tanhf(f[4]), tanhf(f[5]), tanhf(f[6]), tanhf(f[7]));
            o4[2] = make_float4(tanhf(f[8]), tanhf(f[9]), tanhf(f[10]), tanhf(f[11]));
            o4[3] = make_float4(tanhf(f[12]), tanhf(f[13]), tanhf(f[14]), tanhf(f[15]));
        }
    }
}

// ---------------- GAT transform: t = h @ W_gat[hd], plus a_src/a_dst dots ----------------
__global__ void k_gat_t(const float* __restrict__ Wgat, const float* __restrict__ asrc,
                        const float* __restrict__ adst) {
    extern __shared__ float sm[];
    float* xs = sm;              // 128*65
    float* Ws = sm + 128 * XP;   // 64*64
    int tid = threadIdx.x;
    for (int rep = 0; rep < 2; rep++) {
        int nb0 = (blockIdx.x + rep * 256) * 128;
        __syncthreads();
        load_tile64(g_h + (size_t)nb0 * ND, xs);
        const float* xrow = xs + tid * XP;
        for (int hd = 0; hd < NH; hd++) {
            __syncthreads();
            load_w(Wgat + (size_t)hd * ND * ND, Ws, ND * ND);
            __syncthreads();
            float ss = 0.0f, sd = 0.0f;
            float* trow = g_t + ((size_t)(nb0 + tid) * NH + hd) * ND;
#pragma unroll
            for (int c = 0; c < 4; c++) {
                ull acc[8]; acc_init0(acc);
                gemv_acc<ND>(xrow, Ws, c * 16, acc);
                float f[16]; acc_unpack(acc, f);
#pragma unroll
                for (int j = 0; j < 16; j++) {
                    ss += f[j] * __ldg(&asrc[hd * ND + c * 16 + j]);
                    sd += f[j] * __ldg(&adst[hd * ND + c * 16 + j]);
                }
                float4* t4 = reinterpret_cast<float4*>(trow + c * 16);
                t4[0] = make_float4(f[0], f[1], f[2], f[3]);
                t4[1] = make_float4(f[4], f[5], f[6], f[7]);
                t4[2] = make_float4(f[8], f[9], f[10], f[11]);
                t4[3] = make_float4(f[12], f[13], f[14], f[15]);
            }
            g_ssrc[(size_t)(nb0 + tid) * NH + hd] = ss;
            g_sdst[(size_t)(nb0 + tid) * NH + hd] = sd;
        }
    }
}

// ---------------- GAT attention + aggregation: 4 nodes/block, warp = (node, head) ----------------
__global__ void k_gat_attn(const int* __restrict__ adj) {
    __shared__ float s_agg[4][NH][ND];
    int wid = threadIdx.x >> 5, lane = threadIdx.x & 31;
    int ni = wid >> 2, hd = wid & 3;
    int n = (blockIdx.x << 2) + ni;
    int b = n >> 14;  // NV = 2^14

    float score = NEGV;
    int idx = NV;
    if (lane < NK) {
        idx = __ldg(&adj[(size_t)n * NK + lane]);
        if (idx < NV)
            score = __ldg(&g_ssrc[(size_t)n * NH + hd]) +
                    __ldg(&g_sdst[((size_t)(b << 14) + idx) * NH + hd]);
    }
    float mx = score;
#pragma unroll
    for (int o = 16; o > 0; o >>= 1) mx = fmaxf(mx, __shfl_xor_sync(0xffffffffu, mx, o));
    float e = (lane < NK) ? expf(score - mx) : 0.0f;
    float s = e;
#pragma unroll
    for (int o = 16; o > 0; o >>= 1) s += __shfl_xor_sync(0xffffffffu, s, o);
    float attn = e / s;

    float ax = 0.0f, ay = 0.0f;
#pragma unroll
    for (int k = 0; k < NK; k++) {
        int j = __shfl_sync(0xffffffffu, idx, k);
        float a = __shfl_sync(0xffffffffu, attn, k);
        if (j < NV) {
            const float2* tp =
                reinterpret_cast<const float2*>(g_t + (((size_t)(b << 14) + j) * NH + hd) * ND);
            float2 tv = __ldg(tp + lane);
            ax += a * tv.x; ay += a * tv.y;
        }
    }
    s_agg[ni][hd][2 * lane] = ax;
    s_agg[ni][hd][2 * lane + 1] = ay;
    __syncthreads();
    if (threadIdx.x < 256) {
        int nn = threadIdx.x >> 6, j = threadIdx.x & 63;
        float t = s_agg[nn][0][j] + s_agg[nn][1][j] + s_agg[nn][2][j] + s_agg[nn][3][j];
        g_m[((size_t)(blockIdx.x << 2) + nn) * ND + j] = tanhf(t * 0.25f);
    }
}

// ---------------- GRU gates z and r*h ----------------
__global__ void k_gru_zr(const float* __restrict__ Wz, const float* __restrict__ Uz,
                         const float* __restrict__ bz, const float* __restrict__ Wr,
                         const float* __restrict__ Ur, const float* __restrict__ br) {
    extern __shared__ float sm[];
    float* xm = sm;                     // 128*65
    float* xh = sm + 128 * XP;          // 128*65
    float* Wa = xh + 128 * XP;          // 64*64
    float* Wb = Wa + ND * ND;           // 64*64
    int tid = threadIdx.x;
    for (int rep = 0; rep < 2; rep++) {
        int nb0 = (blockIdx.x + rep * 256) * 128;
        int n = nb0 + tid;
        __syncthreads();
        load_tile64(g_m + (size_t)nb0 * ND, xm);
        load_tile64(g_h + (size_t)nb0 * ND, xh);
        load_w(Wz, Wa, ND * ND);
        load_w(Uz, Wb, ND * ND);
        __syncthreads();
        const float* mrow = xm + tid * XP;
        const float* hrow = xh + tid * XP;
        float* zo = g_z + (size_t)n * ND;
#pragma unroll
        for (int c = 0; c < 4; c++) {
            ull acc[8]; acc_initb(bz, c * 16, acc);
            gemv_acc<ND>(mrow, Wa, c * 16, acc);
            gemv_acc<ND>(hrow, Wb, c * 16, acc);
            float f[16]; acc_unpack(acc, f);
            float4* o4 = reinterpret_cast<float4*>(zo + c * 16);
#pragma unroll
            for (int q = 0; q < 4; q++)
                o4[q] = make_float4(sigmoidf_(f[4 * q]), sigmoidf_(f[4 * q + 1]),
                                    sigmoidf_(f[4 * q + 2]), sigmoidf_(f[4 * q + 3]));
        }
        __syncthreads();
        load_w(Wr, Wa, ND * ND);
        load_w(Ur, Wb, ND * ND);
        __syncthreads();
        float* ro = g_rh + (size_t)n * ND;
#pragma unroll
        for (int c = 0; c < 4; c++) {
            ull acc[8]; acc_initb(br, c * 16, acc);
            gemv_acc<ND>(mrow, Wa, c * 16, acc);
            gemv_acc<ND>(hrow, Wb, c * 16, acc);
            float f[16]; acc_unpack(acc, f);
            float4* o4 = reinterpret_cast<float4*>(ro + c * 16);
#pragma unroll
            for (int q = 0; q < 4; q++) {
                float h0 = hrow[c * 16 + 4 * q], h1 = hrow[c * 16 + 4 * q + 1];
                float h2 = hrow[c * 16 + 4 * q + 2], h3 = hrow[c * 16 + 4 * q + 3];
                o4[q] = make_float4(sigmoidf_(f[4 * q]) * h0, sigmoidf_(f[4 * q + 1]) * h1,
                                    sigmoidf_(f[4 * q + 2]) * h2, sigmoidf_(f[4 * q + 3]) * h3);
            }
        }
    }
}

// ---------------- GRU candidate c + state update ----------------
__global__ void k_gru_c(const float* __restrict__ Wc, const float* __restrict__ Uc,
                        const float* __restrict__ bc) {
    extern __shared__ float sm[];
    float* xm = sm;
    float* xr = sm + 128 * XP;
    float* Wa = xr + 128 * XP;
    float* Wb = Wa + ND * ND;
    int tid = threadIdx.x;
    for (int rep = 0; rep < 2; rep++) {
        int nb0 = (blockIdx.x + rep * 256) * 128;
        int n = nb0 + tid;
        __syncthreads();
        load_tile64(g_m + (size_t)nb0 * ND, xm);
        load_tile64(g_rh + (size_t)nb0 * ND, xr);
        load_w(Wc, Wa, ND * ND);
        load_w(Uc, Wb, ND * ND);
        __syncthreads();
        const float* mrow = xm + tid * XP;
        const float* rrow = xr + tid * XP;
        const float4* z4 = reinterpret_cast<const float4*>(g_z + (size_t)n * ND);
        float4* h4 = reinterpret_cast<float4*>(g_h + (size_t)n * ND);
#pragma unroll
        for (int c = 0; c < 4; c++) {
            ull acc[8]; acc_initb(bc, c * 16, acc);
            gemv_acc<ND>(mrow, Wa, c * 16, acc);
            gemv_acc<ND>(rrow, Wb, c * 16, acc);
            float f[16]; acc_unpack(acc, f);
#pragma unroll
            for (int q = 0; q < 4; q++) {
                float4 zv = __ldg(z4 + c * 4 + q);
                float4 hv = h4[c * 4 + q];
                float4 o;
                o.x = (1.0f - zv.x) * hv.x + zv.x * tanhf(f[4 * q]);
                o.y = (1.0f - zv.y) * hv.y + zv.y * tanhf(f[4 * q + 1]);
                o.z = (1.0f - zv.z) * hv.z + zv.z * tanhf(f[4 * q + 2]);
                o.w = (1.0f - zv.w) * hv.w + zv.w * tanhf(f[4 * q + 3]);
                h4[c * 4 + q] = o;
            }
        }
    }
}

// ---------------- decoder -> per-node scalar ----------------
__global__ void k_decoder(const float* __restrict__ W1, const float* __restrict__ b1,
                          const float* __restrict__ W2, const float* __restrict__ b2) {
    extern __shared__ float sm[];
    float* xs = sm;
    float* Ws = sm + 128 * XP;
    int tid = threadIdx.x;
    for (int rep = 0; rep < 2; rep++) {
        int nb0 = (blockIdx.x + rep * 256) * 128;
        __syncthreads();
        load_tile64(g_h + (size_t)nb0 * ND, xs);
        if (rep == 0) load_w(W1, Ws, ND * ND);
        __syncthreads();
        const float* xrow = xs + tid * XP;
        float w = __ldg(&b2[0]);
#pragma unroll
        for (int c = 0; c < 4; c++) {
            ull acc[8]; acc_initb(b1, c * 16, acc);
            gemv_acc<ND>(xrow, Ws, c * 16, acc);
            float f[16]; acc_unpack(acc, f);
#pragma unroll
            for (int j = 0; j < 16; j++) w += tanhf(f[j]) * __ldg(&W2[c * 16 + j]);
        }
        g_nodew[nb0 + tid] = w;
    }
}

// ---------------- edge softmax + flow0; zero inflow ----------------
__global__ void k_normw(const int* __restrict__ adj, const float* __restrict__ demands,
                        float* __restrict__ out_normw, float* __restrict__ out_flow0) {
    int n = blockIdx.x * blockDim.x + threadIdx.x;
    if (n >= NODES) return;
    int b = n >> 14;
    float sc[NK];
    float mx = NEGV;
#pragma unroll
    for (int k = 0; k < NK; k++) {
        int idx = __ldg(&adj[(size_t)n * NK + k]);
        float s = (idx < NV) ? __ldg(&g_nodew[(size_t)(b << 14) + idx]) : NEGV;
        sc[k] = s;
        mx = fmaxf(mx, s);
    }
    float sum = 0.0f;
#pragma unroll
    for (int k = 0; k < NK; k++) { sc[k] = expf(sc[k] - mx); sum += sc[k]; }
    float inv = 1.0f / sum;
    float supply = fmaxf(-__ldg(&demands[n]), 0.0f);
#pragma unroll
    for (int k = 0; k < NK; k++) {
        float nw = sc[k] * inv;
        out_normw[(size_t)n * NK + k] = nw;
        out_flow0[(size_t)n * NK + k] = nw * supply;
    }
    g_inflow[n] = 0.0f;
}

// ---------------- flow iteration ----------------
__global__ void k_scatter(const int* __restrict__ adj, const float* __restrict__ flow) {
    int n = blockIdx.x * blockDim.x + threadIdx.x;
    if (n >= NODES) return;
    int b = n >> 14;
#pragma unroll
    for (int k = 0; k < NK; k++) {
        int idx = __ldg(&adj[(size_t)n * NK + k]);
        if (idx < NV) atomicAdd(&g_inflow[(size_t)(b << 14) + idx], __ldg(&flow[(size_t)n * NK + k]));
    }
}

__global__ void k_update(const float* __restrict__ demands, const float* __restrict__ normw,
                         float* __restrict__ nxt) {
    int n = blockIdx.x * blockDim.x + threadIdx.x;
    if (n >= NODES) return;
    float nf = fmaxf(g_inflow[n] - __ldg(&demands[n]), 0.0f);
    g_inflow[n] = 0.0f;
    const float4* nw4 = reinterpret_cast<const float4*>(normw + (size_t)n * NK);
    float4* o4 = reinterpret_cast<float4*>(nxt + (size_t)n * NK);
#pragma unroll
    for (int k = 0; k < NK / 4; k++) {
        float4 v = __ldg(nw4 + k);
        v.x *= nf; v.y *= nf; v.z *= nf; v.w *= nf;
        o4[k] = v;
    }
}

// ---------------- per-batch quadratic cost ----------------
__global__ void k_cost(const float* __restrict__ flow, float* __restrict__ cost) {
    int b = blockIdx.x >> 6;
    size_t base = (size_t)blockIdx.x * 4096;
    const float4* f4 = reinterpret_cast<const float4*>(flow + base);
    float s = 0.0f;
    for (int i = threadIdx.x; i < 1024; i += 256) {
        float4 v = __ldg(f4 + i);
        s += v.x * v.x + v.y * v.y + v.z * v.z + v.w * v.w;
    }
#pragma unroll
    for (int o = 16; o > 0; o >>= 1) s += __shfl_xor_sync(0xffffffffu, s, o);
    __shared__ float ws[8];
    if ((threadIdx.x & 31) == 0) ws[threadIdx.x >> 5] = s;
    __syncthreads();
    if (threadIdx.x == 0) {
        float t = 0.0f;
        for (int i = 0; i < 8; i++) t += ws[i];
        atomicAdd(&cost[b], t);
    }
}

// ---------------- launch ----------------
#define ENC_SMEM ((128 * 35 + 128 * XP + NDIN * ND + ND * ND) * 4)
#define GATT_SMEM ((128 * XP + ND * ND) * 4)
#define ZR_SMEM ((128 * XP * 2 + 2 * ND * ND) * 4)
#define GC_SMEM ((128 * XP * 2 + 2 * ND * ND) * 4)
#define DEC_SMEM ((128 * XP + ND * ND) * 4)

extern "C" void kernel_launch(void* const* d_in, const int* in_sizes, int n_in,
                              void* d_out, int out_size) {
    const float* emb     = (const float*)d_in[0];
    const float* feat    = (const float*)d_in[1];
    const float* demands = (const float*)d_in[2];
    const int*   adj     = (const int*)d_in[3];
    int wb = (in_sizes[5] == 1) ? 6 : 5;
    const float* W_enc1 = (const float*)d_in[wb + 0];
    const float* b_enc1 = (const float*)d_in[wb + 1];
    const float* W_enc2 = (const float*)d_in[wb + 2];
    const float* b_enc2 = (const float*)d_in[wb + 3];
    const float* W_gat  = (const float*)d_in[wb + 4];
    const float* a_src  = (const float*)d_in[wb + 5];
    const float* a_dst  = (const float*)d_in[wb + 6];
    const float* W_z    = (const float*)d_in[wb + 7];
    const float* U_z    = (const float*)d_in[wb + 8];
    const float* b_z    = (const float*)d_in[wb + 9];
    const float* W_r    = (const float*)d_in[wb + 10];
    const float* U_r    = (const float*)d_in[wb + 11];
    const float* b_r    = (const float*)d_in[wb + 12];
    const float* W_c    = (const float*)d_in[wb + 13];
    const float* U_c    = (const float*)d_in[wb + 14];
    const float* b_c    = (const float*)d_in[wb + 15];
    const float* W_dec1 = (const float*)d_in[wb + 16];
    const float* b_dec1 = (const float*)d_in[wb + 17];
    const float* W_dec2 = (const float*)d_in[wb + 18];
    const float* b_dec2 = (const float*)d_in[wb + 19];

    float* out = (float*)d_out;
    float* out_flow  = out;                                 // [B,V,K] f10
    float* out_cost  = out + (size_t)NB * NV * NK;          // [B]
    float* out_normw = out_cost + NB;                       // [B,V,K]
    float* out_pflow = out_normw + (size_t)NB * NV * NK;    // [B,V,K] f9

    cudaFuncSetAttribute(k_encoder, cudaFuncAttributeMaxDynamicSharedMemorySize, ENC_SMEM);
    cudaFuncSetAttribute(k_gat_t, cudaFuncAttributeMaxDynamicSharedMemorySize, GATT_SMEM);
    cudaFuncSetAttribute(k_gru_zr, cudaFuncAttributeMaxDynamicSharedMemorySize, ZR_SMEM);
    cudaFuncSetAttribute(k_gru_c, cudaFuncAttributeMaxDynamicSharedMemorySize, GC_SMEM);
    cudaFuncSetAttribute(k_decoder, cudaFuncAttributeMaxDynamicSharedMemorySize, DEC_SMEM);

    k_encoder<<<256, 128, ENC_SMEM>>>(emb, feat, W_enc1, b_enc1, W_enc2, b_enc2);
    for (int l = 0; l < NL; l++) {
        k_gat_t<<<256, 128, GATT_SMEM>>>(W_gat, a_src, a_dst);
        k_gat_attn<<<NODES / 4, 512>>>(adj);
        k_gru_zr<<<256, 128, ZR_SMEM>>>(W_z, U_z, b_z, W_r, U_r, b_r);
        k_gru_c<<<256, 128, GC_SMEM>>>(W_c, U_c, b_c);
    }
    k_decoder<<<256, 128, DEC_SMEM>>>(W_dec1, b_dec1, W_dec2, b_dec2);
    k_normw<<<256, 256>>>(adj, demands, out_normw, out_flow);

    float* cur = out_flow;
    float* nxt = out_pflow;
    for (int it = 0; it < NITERS; it++) {
        k_scatter<<<256, 256>>>(adj, cur);
        k_update<<<256, 256>>>(demands, out_normw, nxt);
        float* tmp = cur; cur = nxt; nxt = tmp;
    }

    cudaMemsetAsync(out_cost, 0, NB * sizeof(float), 0);
    k_cost<<<256, 256>>>(out_flow, out_cost);
}

// round 3
// speedup vs baseline: 3.0772x; 1.4521x over previous
#include <cuda_runtime.h>
#include <math.h>

typedef unsigned long long ull;

#define NB 4
#define NV 16384
#define NK 16
#define NE 32
#define ND 64
#define NH 4
#define NL 2
#define NEGV (-1e9f)
#define NODES (NB * NV)

// ---------------- scratch ----------------
__device__ float g_h[NODES * ND];
__device__ float g_t[(size_t)NODES * NH * ND];
__device__ float g_ssrc[NODES * NH];
__device__ float g_sdst[NODES * NH];
__device__ float g_m[NODES * ND];
__device__ float g_nodew[NODES];
__device__ float g_sn[NODES];
__device__ float g_inflowA[NODES];
__device__ float g_inflowB[NODES];

__device__ __forceinline__ float sigmoidf_(float x) { return 1.0f / (1.0f + expf(-x)); }

__device__ __forceinline__ ull pack2(float x) {
    ull r; asm("mov.b64 %0, {%1, %1};" : "=l"(r) : "f"(x)); return r;
}
__device__ __forceinline__ ull packf2(float a, float b) {
    ull r; asm("mov.b64 %0, {%1, %2};" : "=l"(r) : "f"(a), "f"(b)); return r;
}
__device__ __forceinline__ void ffma2(ull& d, ull a, ull b) {
    asm("fma.rn.f32x2 %0, %1, %2, %0;" : "+l"(d) : "l"(a), "l"(b));
}
__device__ __forceinline__ float2 unpk(ull v) {
    float2 f; asm("mov.b64 {%0, %1}, %2;" : "=f"(f.x), "=f"(f.y) : "l"(v)); return f;
}
__device__ __forceinline__ void st4(float* p, float a, float b, float c, float d) {
    *reinterpret_cast<float4*>(p) = make_float4(a, b, c, d);
}

// load weight matrix [K][64] row-major into smem, 128 threads
__device__ __forceinline__ void load_w(const float* __restrict__ g, float* ws, int nfloats) {
    const float4* g4 = reinterpret_cast<const float4*>(g);
    float4* s4 = reinterpret_cast<float4*>(ws);
    for (int i = threadIdx.x; i < (nfloats >> 2); i += 128) s4[i] = __ldg(g4 + i);
}

// stage 128 node rows of 64 floats TRANSPOSED into xs[64][128] (thread = node)
__device__ __forceinline__ void stage_xT(const float* __restrict__ g, float* xs) {
    int tid = threadIdx.x;
    const float4* g4 = reinterpret_cast<const float4*>(g + (size_t)tid * ND);
#pragma unroll
    for (int c = 0; c < 16; c++) {
        float4 v = __ldg(g4 + c);
        xs[(4 * c + 0) * 128 + tid] = v.x;
        xs[(4 * c + 1) * 128 + tid] = v.y;
        xs[(4 * c + 2) * 128 + tid] = v.z;
        xs[(4 * c + 3) * 128 + tid] = v.w;
    }
}

// register-tiled pass: acc[j*4+p] (cols tc8+j, node-pair p) += xs^T @ ws
template <int K>
__device__ __forceinline__ void gpass(const float* __restrict__ xs, const float* __restrict__ ws,
                                      ull acc[32], int tn8, int tc8) {
#pragma unroll 4
    for (int k = 0; k < K; k++) {
        const ulonglong2* xr = reinterpret_cast<const ulonglong2*>(xs + k * 128 + tn8);
        ulonglong2 xa = xr[0], xb = xr[1];
        const float4* wr = reinterpret_cast<const float4*>(ws + k * ND + tc8);
        float4 wa = wr[0], wb = wr[1];
        ull w0 = pack2(wa.x), w1 = pack2(wa.y), w2 = pack2(wa.z), w3 = pack2(wa.w);
        ull w4 = pack2(wb.x), w5 = pack2(wb.y), w6 = pack2(wb.z), w7 = pack2(wb.w);
#define FFJ(j, wv)                    \
    ffma2(acc[(j)*4 + 0], wv, xa.x);  \
    ffma2(acc[(j)*4 + 1], wv, xa.y);  \
    ffma2(acc[(j)*4 + 2], wv, xb.x);  \
    ffma2(acc[(j)*4 + 3], wv, xb.y);
        FFJ(0, w0) FFJ(1, w1) FFJ(2, w2) FFJ(3, w3)
        FFJ(4, w4) FFJ(5, w5) FFJ(6, w6) FFJ(7, w7)
#undef FFJ
    }
}

__device__ __forceinline__ void acc_bias(ull acc[32], const float* __restrict__ b, int tc8) {
#pragma unroll
    for (int j = 0; j < 8; j++) {
        ull v = pack2(__ldg(&b[tc8 + j]));
        acc[j * 4 + 0] = v; acc[j * 4 + 1] = v; acc[j * 4 + 2] = v; acc[j * 4 + 3] = v;
    }
}
__device__ __forceinline__ void acc_zero(ull acc[32]) {
#pragma unroll
    for (int i = 0; i < 32; i++) acc[i] = 0ull;
}

// ---------------- encoder ----------------
#define ENC_SMEM ((34 * 128 + 34 * 64 + 64 * 128 + 64 * 64) * 4)
__global__ void __launch_bounds__(128, 3)
k_encoder(const float* __restrict__ emb, const float* __restrict__ feat,
          const float* __restrict__ W1, const float* __restrict__ b1,
          const float* __restrict__ W2, const float* __restrict__ b2) {
    extern __shared__ float sm[];
    float* xs1 = sm;                   // [34][128]
    float* W1s = xs1 + 34 * 128;       // [34][64]
    float* xs2 = W1s + 34 * 64;        // [64][128]
    float* W2s = xs2 + 64 * 128;       // [64][64]
    int tid = threadIdx.x;
    int nb0 = blockIdx.x * 128;
    int tn8 = (tid >> 3) * 8, tc8 = (tid & 7) * 8;

    {  // stage [emb|feat] transposed
        const float4* e4 = reinterpret_cast<const float4*>(emb + (size_t)(nb0 + tid) * NE);
#pragma unroll
        for (int c = 0; c < 8; c++) {
            float4 v = __ldg(e4 + c);
            xs1[(4 * c + 0) * 128 + tid] = v.x;
            xs1[(4 * c + 1) * 128 + tid] = v.y;
            xs1[(4 * c + 2) * 128 + tid] = v.z;
            xs1[(4 * c + 3) * 128 + tid] = v.w;
        }
        float2 fv = __ldg(reinterpret_cast<const float2*>(feat + (size_t)(nb0 + tid) * 2));
        xs1[32 * 128 + tid] = fv.x;
        xs1[33 * 128 + tid] = fv.y;
    }
    load_w(W1, W1s, 34 * 64);
    load_w(W2, W2s, 64 * 64);
    // zero flow inflow buffers (one elem per thread, 512*128 = NODES)
    g_inflowA[nb0 + tid] = 0.0f;
    g_inflowB[nb0 + tid] = 0.0f;
    __syncthreads();

    ull acc[32];
    acc_bias(acc, b1, tc8);
    gpass<34>(xs1, W1s, acc, tn8, tc8);
    // tanh -> xs2 transposed
#pragma unroll
    for (int j = 0; j < 8; j++)
#pragma unroll
        for (int p = 0; p < 4; p++) {
            float2 v = unpk(acc[j * 4 + p]);
            *reinterpret_cast<ull*>(xs2 + (tc8 + j) * 128 + tn8 + 2 * p) =
                packf2(tanhf(v.x), tanhf(v.y));
        }
    __syncthreads();

    acc_bias(acc, b2, tc8);
    gpass<64>(xs2, W2s, acc, tn8, tc8);
#pragma unroll
    for (int p = 0; p < 4; p++) {
        float o0[8], o1[8];
#pragma unroll
        for (int j = 0; j < 8; j++) {
            float2 v = unpk(acc[j * 4 + p]);
            o0[j] = tanhf(v.x); o1[j] = tanhf(v.y);
        }
        float* r0 = g_h + (size_t)(nb0 + tn8 + 2 * p) * ND + tc8;
        st4(r0, o0[0], o0[1], o0[2], o0[3]); st4(r0 + 4, o0[4], o0[5], o0[6], o0[7]);
        float* r1 = r0 + ND;
        st4(r1, o1[0], o1[1], o1[2], o1[3]); st4(r1 + 4, o1[4], o1[5], o1[6], o1[7]);
    }
}

// ---------------- GAT transform ----------------
#define GAT_SMEM ((64 * 128 + 64 * 64) * 4)
__global__ void __launch_bounds__(128, 3)
k_gat_t(const float* __restrict__ Wgat, const float* __restrict__ asrc,
        const float* __restrict__ adst) {
    extern __shared__ float sm[];
    float* xs = sm;             // [64][128]
    float* Ws = sm + 64 * 128;  // [64][64]
    int tid = threadIdx.x;
    int nb0 = blockIdx.x * 128;
    int tn8 = (tid >> 3) * 8, tc8 = (tid & 7) * 8;
    stage_xT(g_h + (size_t)nb0 * ND, xs);

    for (int hd = 0; hd < NH; hd++) {
        __syncthreads();
        load_w(Wgat + (size_t)hd * ND * ND, Ws, ND * ND);
        __syncthreads();
        ull acc[32];
        acc_zero(acc);
        gpass<64>(xs, Ws, acc, tn8, tc8);

        float as_[8], ad_[8];
#pragma unroll
        for (int j = 0; j < 8; j++) {
            as_[j] = __ldg(&asrc[hd * ND + tc8 + j]);
            ad_[j] = __ldg(&adst[hd * ND + tc8 + j]);
        }
        float ss8[8], sd8[8];
#pragma unroll
        for (int p = 0; p < 4; p++) {
            float o0[8], o1[8];
            float s0 = 0.f, s1 = 0.f, d0 = 0.f, d1 = 0.f;
#pragma unroll
            for (int j = 0; j < 8; j++) {
                float2 v = unpk(acc[j * 4 + p]);
                o0[j] = v.x; o1[j] = v.y;
                s0 += v.x * as_[j]; d0 += v.x * ad_[j];
                s1 += v.y * as_[j]; d1 += v.y * ad_[j];
            }
            float* t0 = g_t + ((size_t)(nb0 + tn8 + 2 * p) * NH + hd) * ND + tc8;
            st4(t0, o0[0], o0[1], o0[2], o0[3]); st4(t0 + 4, o0[4], o0[5], o0[6], o0[7]);
            float* t1 = t0 + NH * ND;
            st4(t1, o1[0], o1[1], o1[2], o1[3]); st4(t1 + 4, o1[4], o1[5], o1[6], o1[7]);
            ss8[2 * p] = s0; ss8[2 * p + 1] = s1;
            sd8[2 * p] = d0; sd8[2 * p + 1] = d1;
        }
#pragma unroll
        for (int q = 0; q < 8; q++) {
#pragma unroll
            for (int off = 4; off > 0; off >>= 1) {
                ss8[q] += __shfl_xor_sync(0xffffffffu, ss8[q], off);
                sd8[q] += __shfl_xor_sync(0xffffffffu, sd8[q], off);
            }
        }
        if ((tid & 7) == 0) {
#pragma unroll
            for (int q = 0; q < 8; q++) {
                g_ssrc[(size_t)(nb0 + tn8 + q) * NH + hd] = ss8[q];
                g_sdst[(size_t)(nb0 + tn8 + q) * NH + hd] = sd8[q];
            }
        }
    }
}

// ---------------- GAT attention + aggregation ----------------
__global__ void k_gat_attn(const int* __restrict__ adj) {
    __shared__ float s_agg[4][NH][ND];
    int wid = threadIdx.x >> 5, lane = threadIdx.x & 31;
    int ni = wid >> 2, hd = wid & 3;
    int n = (blockIdx.x << 2) + ni;
    int b = n >> 14;

    float score = NEGV;
    int idx = NV;
    if (lane < NK) {
        idx = __ldg(&adj[(size_t)n * NK + lane]);
        if (idx < NV)
            score = __ldg(&g_ssrc[(size_t)n * NH + hd]) +
                    __ldg(&g_sdst[((size_t)(b << 14) + idx) * NH + hd]);
    }
    float mx = score;
#pragma unroll
    for (int o = 16; o > 0; o >>= 1) mx = fmaxf(mx, __shfl_xor_sync(0xffffffffu, mx, o));
    float e = (lane < NK) ? expf(score - mx) : 0.0f;
    float s = e;
#pragma unroll
    for (int o = 16; o > 0; o >>= 1) s += __shfl_xor_sync(0xffffffffu, s, o);
    float attn = e / s;

    float ax = 0.0f, ay = 0.0f;
#pragma unroll
    for (int k = 0; k < NK; k++) {
        int j = __shfl_sync(0xffffffffu, idx, k);
        float a = __shfl_sync(0xffffffffu, attn, k);
        if (j < NV) {
            const float2* tp =
                reinterpret_cast<const float2*>(g_t + (((size_t)(b << 14) + j) * NH + hd) * ND);
            float2 tv = __ldg(tp + lane);
            ax += a * tv.x; ay += a * tv.y;
        }
    }
    s_agg[ni][hd][2 * lane] = ax;
    s_agg[ni][hd][2 * lane + 1] = ay;
    __syncthreads();
    if (threadIdx.x < 256) {
        int nn = threadIdx.x >> 6, j = threadIdx.x & 63;
        float t = s_agg[nn][0][j] + s_agg[nn][1][j] + s_agg[nn][2][j] + s_agg[nn][3][j];
        g_m[((size_t)(blockIdx.x << 2) + nn) * ND + j] = tanhf(t * 0.25f);
    }
}

// ---------------- fused GRU ----------------
#define GRU_SMEM ((3 * 64 * 128 + 64 * 64) * 4)
__global__ void __launch_bounds__(128, 2)
k_gru(const float* __restrict__ Wz, const float* __restrict__ Uz, const float* __restrict__ bz,
      const float* __restrict__ Wr, const float* __restrict__ Ur, const float* __restrict__ br,
      const float* __restrict__ Wc, const float* __restrict__ Uc, const float* __restrict__ bc) {
    extern __shared__ float sm[];
    float* xm = sm;               // [64][128]
    float* xh = sm + 64 * 128;
    float* xrh = sm + 2 * 64 * 128;
    float* Ws = sm + 3 * 64 * 128;  // [64][64]
    int tid = threadIdx.x;
    int nb0 = blockIdx.x * 128;
    int tn8 = (tid >> 3) * 8, tc8 = (tid & 7) * 8;

    stage_xT(g_m + (size_t)nb0 * ND, xm);
    stage_xT(g_h + (size_t)nb0 * ND, xh);
    load_w(Wz, Ws, ND * ND);
    __syncthreads();

    ull acc[32], zp[32];
    // ---- z ----
    acc_bias(acc, bz, tc8);
    gpass<64>(xm, Ws, acc, tn8, tc8);
    __syncthreads();
    load_w(Uz, Ws, ND * ND);
    __syncthreads();
    gpass<64>(xh, Ws, acc, tn8, tc8);
#pragma unroll
    for (int i = 0; i < 32; i++) {
        float2 v = unpk(acc[i]);
        zp[i] = packf2(sigmoidf_(v.x), sigmoidf_(v.y));
    }
    // ---- r, rh ----
    __syncthreads();
    load_w(Wr, Ws, ND * ND);
    __syncthreads();
    acc_bias(acc, br, tc8);
    gpass<64>(xm, Ws, acc, tn8, tc8);
    __syncthreads();
    load_w(Ur, Ws, ND * ND);
    __syncthreads();
    gpass<64>(xh, Ws, acc, tn8, tc8);
#pragma unroll
    for (int j = 0; j < 8; j++)
#pragma unroll
        for (int p = 0; p < 4; p++) {
            float2 rv = unpk(acc[j * 4 + p]);
            float2 hv = unpk(*reinterpret_cast<const ull*>(xh + (tc8 + j) * 128 + tn8 + 2 * p));
            *reinterpret_cast<ull*>(xrh + (tc8 + j) * 128 + tn8 + 2 * p) =
                packf2(sigmoidf_(rv.x) * hv.x, sigmoidf_(rv.y) * hv.y);
        }
    // ---- c, h' ----
    __syncthreads();
    load_w(Wc, Ws, ND * ND);
    __syncthreads();
    acc_bias(acc, bc, tc8);
    gpass<64>(xm, Ws, acc, tn8, tc8);
    __syncthreads();
    load_w(Uc, Ws, ND * ND);
    __syncthreads();
    gpass<64>(xrh, Ws, acc, tn8, tc8);
#pragma unroll
    for (int p = 0; p < 4; p++) {
        float o0[8], o1[8];
#pragma unroll
        for (int j = 0; j < 8; j++) {
            float2 cv = unpk(acc[j * 4 + p]);
            float2 hv = unpk(*reinterpret_cast<const ull*>(xh + (tc8 + j) * 128 + tn8 + 2 * p));
            float2 zv = unpk(zp[j * 4 + p]);
            o0[j] = hv.x + zv.x * (tanhf(cv.x) - hv.x);
            o1[j] = hv.y + zv.y * (tanhf(cv.y) - hv.y);
        }
        float* r0 = g_h + (size_t)(nb0 + tn8 + 2 * p) * ND + tc8;
        st4(r0, o0[0], o0[1], o0[2], o0[3]); st4(r0 + 4, o0[4], o0[5], o0[6], o0[7]);
        float* r1 = r0 + ND;
        st4(r1, o1[0], o1[1], o1[2], o1[3]); st4(r1 + 4, o1[4], o1[5], o1[6], o1[7]);
    }
}

// ---------------- decoder ----------------
#define DEC_SMEM ((64 * 128 + 64 * 64) * 4)
__global__ void __launch_bounds__(128, 3)
k_decoder(const float* __restrict__ W1, const float* __restrict__ b1,
          const float* __restrict__ W2, const float* __restrict__ b2) {
    extern __shared__ float sm[];
    float* xs = sm;
    float* Ws = sm + 64 * 128;
    int tid = threadIdx.x;
    int nb0 = blockIdx.x * 128;
    int tn8 = (tid >> 3) * 8, tc8 = (tid & 7) * 8;
    stage_xT(g_h + (size_t)nb0 * ND, xs);
    load_w(W1, Ws, ND * ND);
    __syncthreads();
    ull acc[32];
    acc_bias(acc, b1, tc8);
    gpass<64>(xs, Ws, acc, tn8, tc8);
    float w2_[8];
#pragma unroll
    for (int j = 0; j < 8; j++) w2_[j] = __ldg(&W2[tc8 + j]);
    float pw[8];
#pragma unroll
    for (int p = 0; p < 4; p++) {
        float s0 = 0.f, s1 = 0.f;
#pragma unroll
        for (int j = 0; j < 8; j++) {
            float2 v = unpk(acc[j * 4 + p]);
            s0 += tanhf(v.x) * w2_[j];
            s1 += tanhf(v.y) * w2_[j];
        }
        pw[2 * p] = s0; pw[2 * p + 1] = s1;
    }
#pragma unroll
    for (int q = 0; q < 8; q++)
#pragma unroll
        for (int off = 4; off > 0; off >>= 1)
            pw[q] += __shfl_xor_sync(0xffffffffu, pw[q], off);
    if ((tid & 7) == 0) {
        float b2v = __ldg(&b2[0]);
#pragma unroll
        for (int q = 0; q < 8; q++) g_nodew[nb0 + tn8 + q] = pw[q] + b2v;
    }
}

// ---------------- edge softmax + sumsq + flow0 scatter ----------------
__global__ void k_normw(const int* __restrict__ adj, const float* __restrict__ demands,
                        float* __restrict__ out_normw) {
    int n = blockIdx.x * blockDim.x + threadIdx.x;
    int b = n >> 14;
    int base = b << 14;
    int idxv[NK];
    float sc[NK];
    float mx = NEGV;
#pragma unroll
    for (int k = 0; k < NK; k++) {
        int idx = __ldg(&adj[(size_t)n * NK + k]);
        idxv[k] = idx;
        float s = (idx < NV) ? __ldg(&g_nodew[(size_t)base + idx]) : NEGV;
        sc[k] = s;
        mx = fmaxf(mx, s);
    }
    float sum = 0.0f;
#pragma unroll
    for (int k = 0; k < NK; k++) { sc[k] = expf(sc[k] - mx); sum += sc[k]; }
    float inv = 1.0f / sum;
    float nf0 = fmaxf(-__ldg(&demands[n]), 0.0f);
    float sn = 0.0f;
#pragma unroll
    for (int k = 0; k < NK; k++) {
        float nw = sc[k] * inv;
        sc[k] = nw;
        sn += nw * nw;
        out_normw[(size_t)n * NK + k] = nw;
    }
    g_sn[n] = sn;
#pragma unroll
    for (int k = 0; k < NK; k++)
        if (idxv[k] < NV) atomicAdd(&g_inflowA[base + idxv[k]], sc[k] * nf0);
}

// ---------------- fused flow iteration ----------------
__global__ void k_flow_iter(const int* __restrict__ adj, const float* __restrict__ demands,
                            const float* __restrict__ normw, float* __restrict__ cur,
                            float* __restrict__ nxt, float* __restrict__ store) {
    int n = blockIdx.x * blockDim.x + threadIdx.x;
    int base = (n >> 14) << 14;
    float nf = fmaxf(cur[n] - __ldg(&demands[n]), 0.0f);
    cur[n] = 0.0f;
#pragma unroll
    for (int k = 0; k < NK; k++) {
        int idx = __ldg(&adj[(size_t)n * NK + k]);
        float f = __ldg(&normw[(size_t)n * NK + k]) * nf;
        if (store) store[(size_t)n * NK + k] = f;
        if (idx < NV) atomicAdd(&nxt[base + idx], f);
    }
}

// ---------------- final flow + cost ----------------
__global__ void k_flow_last(const float* __restrict__ demands, const float* __restrict__ normw,
                            float* __restrict__ cur, float* __restrict__ out_flow,
                            float* __restrict__ cost) {
    int n = blockIdx.x * blockDim.x + threadIdx.x;
    int b = n >> 14;
    float nf = fmaxf(cur[n] - __ldg(&demands[n]), 0.0f);
    cur[n] = 0.0f;
    const float4* nw4 = reinterpret_cast<const float4*>(normw + (size_t)n * NK);
    float4* o4 = reinterpret_cast<float4*>(out_flow + (size_t)n * NK);
#pragma unroll
    for (int k = 0; k < 4; k++) {
        float4 v = __ldg(nw4 + k);
        v.x *= nf; v.y *= nf; v.z *= nf; v.w *= nf;
        o4[k] = v;
    }
    float val = nf * nf * __ldg(&g_sn[n]);
#pragma unroll
    for (int o = 16; o > 0; o >>= 1) val += __shfl_xor_sync(0xffffffffu, val, o);
    __shared__ float ws[8];
    if ((threadIdx.x & 31) == 0) ws[threadIdx.x >> 5] = val;
    __syncthreads();
    if (threadIdx.x == 0) {
        float t = 0.0f;
#pragma unroll
        for (int i = 0; i < 8; i++) t += ws[i];
        atomicAdd(&cost[b], t);
    }
}

// ---------------- launch ----------------
extern "C" void kernel_launch(void* const* d_in, const int* in_sizes, int n_in,
                              void* d_out, int out_size) {
    const float* emb     = (const float*)d_in[0];
    const float* feat    = (const float*)d_in[1];
    const float* demands = (const float*)d_in[2];
    const int*   adj     = (const int*)d_in[3];
    int wb = (in_sizes[5] == 1) ? 6 : 5;
    const float* W_enc1 = (const float*)d_in[wb + 0];
    const float* b_enc1 = (const float*)d_in[wb + 1];
    const float* W_enc2 = (const float*)d_in[wb + 2];
    const float* b_enc2 = (const float*)d_in[wb + 3];
    const float* W_gat  = (const float*)d_in[wb + 4];
    const float* a_src  = (const float*)d_in[wb + 5];
    const float* a_dst  = (const float*)d_in[wb + 6];
    const float* W_z    = (const float*)d_in[wb + 7];
    const float* U_z    = (const float*)d_in[wb + 8];
    const float* b_z    = (const float*)d_in[wb + 9];
    const float* W_r    = (const float*)d_in[wb + 10];
    const float* U_r    = (const float*)d_in[wb + 11];
    const float* b_r    = (const float*)d_in[wb + 12];
    const float* W_c    = (const float*)d_in[wb + 13];
    const float* U_c    = (const float*)d_in[wb + 14];
    const float* b_c    = (const float*)d_in[wb + 15];
    const float* W_dec1 = (const float*)d_in[wb + 16];
    const float* b_dec1 = (const float*)d_in[wb + 17];
    const float* W_dec2 = (const float*)d_in[wb + 18];
    const float* b_dec2 = (const float*)d_in[wb + 19];

    float* out = (float*)d_out;
    float* out_flow  = out;                               // [B,V,K] f10
    float* out_cost  = out + (size_t)NB * NV * NK;        // [B]
    float* out_normw = out_cost + NB;                     // [B,V,K]
    float* out_pflow = out_normw + (size_t)NB * NV * NK;  // [B,V,K] f9

    float *pA, *pB;
    cudaGetSymbolAddress((void**)&pA, g_inflowA);
    cudaGetSymbolAddress((void**)&pB, g_inflowB);

    cudaFuncSetAttribute(k_encoder, cudaFuncAttributeMaxDynamicSharedMemorySize, ENC_SMEM);
    cudaFuncSetAttribute(k_gat_t, cudaFuncAttributeMaxDynamicSharedMemorySize, GAT_SMEM);
    cudaFuncSetAttribute(k_gru, cudaFuncAttributeMaxDynamicSharedMemorySize, GRU_SMEM);
    cudaFuncSetAttribute(k_decoder, cudaFuncAttributeMaxDynamicSharedMemorySize, DEC_SMEM);

    k_encoder<<<512, 128, ENC_SMEM>>>(emb, feat, W_enc1, b_enc1, W_enc2, b_enc2);
    for (int l = 0; l < NL; l++) {
        k_gat_t<<<512, 128, GAT_SMEM>>>(W_gat, a_src, a_dst);
        k_gat_attn<<<NODES / 4, 512>>>(adj);
        k_gru<<<512, 128, GRU_SMEM>>>(W_z, U_z, b_z, W_r, U_r, b_r, W_c, U_c, b_c);
    }
    k_decoder<<<512, 128, DEC_SMEM>>>(W_dec1, b_dec1, W_dec2, b_dec2);
    k_normw<<<256, 256>>>(adj, demands, out_normw);

    float* cur = pA;
    float* nxt = pB;
    for (int it = 0; it < 9; it++) {
        k_flow_iter<<<256, 256>>>(adj, demands, out_normw, cur, nxt,
                                  (it == 8) ? out_pflow : nullptr);
        float* tmp = cur; cur = nxt; nxt = tmp;
    }
    cudaMemsetAsync(out_cost, 0, NB * sizeof(float), 0);
    k_flow_last<<<256, 256>>>(demands, out_normw, cur, out_flow, out_cost);
}